// round 6
// baseline (speedup 1.0000x reference)
#include <cuda_runtime.h>

// FastQuantumLLMOptimized: per-position cross-head attention.
// x: [16384, 32, 128] f32, patterns: [32,128] f32.
//   xh = x_pos * patterns ; s = xh xh^T / sqrt(128); a = softmax(s); out = a xh
//
// ONE WARP per position (CTA = 2 warps). fp32 with packed fma.rn.f32x2.
// Gram symmetry: phase 2 computes only upper-triangle 4x4 tiles (36/64),
// mirrored into smem; softmax is one-lane-per-row with zero shuffles.
//
// Swizzle: xh float4 granules at h*32 + (c ^ ((h>>2)&7)).  Property: within
// any 8-lane LDS phase group, distinct row-blocks -> distinct bank groups and
// equal rows -> broadcast, so ANY lane->tile assignment is conflict-free.
// Scores/attn buffer stride 36: row reads (granule (9l+t)%8) and transposed
// column writes (bank (4g+l)%32) are conflict-free.

#define NHEADS 32
#define HD 128
#define SC_ROW 36

__device__ __forceinline__ unsigned long long pack2(float lo, float hi) {
    unsigned long long r;
    asm("mov.b64 %0, {%1, %2};" : "=l"(r) : "f"(lo), "f"(hi));
    return r;
}
__device__ __forceinline__ float2 unpack2(unsigned long long v) {
    float2 r;
    asm("mov.b64 {%0, %1}, %2;" : "=f"(r.x), "=f"(r.y) : "l"(v));
    return r;
}
__device__ __forceinline__ void fma2(unsigned long long &acc,
                                     unsigned long long a,
                                     unsigned long long b) {
    asm("fma.rn.f32x2 %0, %1, %2, %0;" : "+l"(acc) : "l"(a), "l"(b));
}

__global__ __launch_bounds__(64)
void fq_attn_kernel(const float* __restrict__ x,
                    const float* __restrict__ patterns,
                    float* __restrict__ out, int npos)
{
    __shared__ __align__(16) float4 s_xh4[2][NHEADS * 32];          // 2 x 16 KB
    __shared__ __align__(16) float  s_sc [2][NHEADS * SC_ROW + 4];  // 2 x ~4.6 KB

    const int lane = threadIdx.x & 31;
    const int w    = threadIdx.x >> 5;
    const long long pos = 2LL * blockIdx.x + w;
    if (pos >= npos) return;

    float4* xh = s_xh4[w];
    float*  sc = s_sc[w];

    // ---------------- Phase 1: load + modulate -> swizzled smem ------------
    {
        const float4* x4 = reinterpret_cast<const float4*>(x + pos * (NHEADS * HD));
        const float4* p4 = reinterpret_cast<const float4*>(patterns);
        #pragma unroll 8
        for (int h = 0; h < 32; h++) {
            float4 xv = x4[h * 32 + lane];
            float4 pv = __ldg(&p4[h * 32 + lane]);
            float4 r;
            r.x = xv.x * pv.x; r.y = xv.y * pv.y;
            r.z = xv.z * pv.z; r.w = xv.w * pv.w;
            xh[h * 32 + (lane ^ ((h >> 2) & 7))] = r;
        }
    }
    __syncwarp();

    // ---------------- Phase 2 pass 1: 32 upper/diag 4x4 tiles --------------
    // lane -> tile (r, cb), cb >= r, excluding tiles (0, 4..7).
    // Row lengths: r=0:4 (cb 0..3), r=1:7, r=2:6, ..., r=7:1.
    {
        const int r = (lane >= 4) + (lane >= 11) + (lane >= 17) + (lane >= 22)
                    + (lane >= 26) + (lane >= 29) + (lane >= 31);
        const int start = (r == 0) ? 0 : (4 + (r - 1) * 8 - ((r - 1) * r) / 2);
        const int cb = (r == 0) ? lane : (r + lane - start);

        unsigned long long acc[4][4];
        #pragma unroll
        for (int i = 0; i < 4; i++)
            #pragma unroll
            for (int j = 0; j < 4; j++) acc[i][j] = 0ULL;

        #pragma unroll 4
        for (int c = 0; c < 32; c++) {
            ulonglong2 a[4], b[4];
            #pragma unroll
            for (int i = 0; i < 4; i++)
                a[i] = *reinterpret_cast<const ulonglong2*>(&xh[(4 * r + i) * 32 + (c ^ r)]);
            #pragma unroll
            for (int j = 0; j < 4; j++)
                b[j] = *reinterpret_cast<const ulonglong2*>(&xh[(4 * cb + j) * 32 + (c ^ cb)]);
            #pragma unroll
            for (int i = 0; i < 4; i++)
                #pragma unroll
                for (int j = 0; j < 4; j++) {
                    fma2(acc[i][j], a[i].x, b[j].x);
                    fma2(acc[i][j], a[i].y, b[j].y);
                }
        }
        #pragma unroll
        for (int i = 0; i < 4; i++)
            #pragma unroll
            for (int j = 0; j < 4; j++) {
                float2 u = unpack2(acc[i][j]);
                float v = u.x + u.y;
                sc[(4 * r + i) * SC_ROW + 4 * cb + j] = v;   // upper
                sc[(4 * cb + j) * SC_ROW + 4 * r + i] = v;   // mirror
            }
    }

    // ---------------- Phase 2 pass 2: tiles (0, 4..7) as 2 elems/lane ------
    // rows 0..3 x cols 16..31; per-lane rotated chunk order keeps LDS
    // conflict-free (bank group = (c+rot)^swz distinct per phase group).
    {
        const int h2  = lane & 3;
        const int g2  = 16 + (lane >> 2);          // 16..23
        const int rot = lane & 7;
        const int s0  = g2 >> 2;                   // 4 or 5
        const int s1  = (g2 + 8) >> 2;             // 6 or 7

        unsigned long long acc0 = 0ULL, acc1 = 0ULL;
        #pragma unroll 4
        for (int c = 0; c < 32; c++) {
            const int cl = (c + rot) & 31;
            ulonglong2 a  = *reinterpret_cast<const ulonglong2*>(&xh[h2 * 32 + cl]);
            ulonglong2 b0 = *reinterpret_cast<const ulonglong2*>(&xh[g2 * 32 + (cl ^ s0)]);
            ulonglong2 b1 = *reinterpret_cast<const ulonglong2*>(&xh[(g2 + 8) * 32 + (cl ^ s1)]);
            fma2(acc0, a.x, b0.x); fma2(acc0, a.y, b0.y);
            fma2(acc1, a.x, b1.x); fma2(acc1, a.y, b1.y);
        }
        float2 u0 = unpack2(acc0), u1 = unpack2(acc1);
        float f0 = u0.x + u0.y, f1 = u1.x + u1.y;
        sc[h2 * SC_ROW + g2]       = f0;
        sc[g2 * SC_ROW + h2]       = f0;
        sc[h2 * SC_ROW + g2 + 8]   = f1;
        sc[(g2 + 8) * SC_ROW + h2] = f1;
    }
    __syncwarp();

    // ---------------- Phase 3: softmax, one lane per row, no shfl ----------
    {
        float v[32];
        #pragma unroll
        for (int t = 0; t < 8; t++) {
            float4 q = *reinterpret_cast<const float4*>(&sc[lane * SC_ROW + 4 * t]);
            v[4 * t + 0] = q.x * 0.08838834764831845f;
            v[4 * t + 1] = q.y * 0.08838834764831845f;
            v[4 * t + 2] = q.z * 0.08838834764831845f;
            v[4 * t + 3] = q.w * 0.08838834764831845f;
        }
        float m = v[0];
        #pragma unroll
        for (int g = 1; g < 32; g++) m = fmaxf(m, v[g]);
        float s = 0.0f;
        #pragma unroll
        for (int g = 0; g < 32; g++) { v[g] = __expf(v[g] - m); s += v[g]; }
        const float inv = 1.0f / s;

        __syncwarp();   // all rows read before overwriting buffer as attn^T
        #pragma unroll
        for (int g = 0; g < 32; g++)
            sc[g * SC_ROW + lane] = v[g] * inv;   // attn^T: [g][h]
    }
    __syncwarp();

    // ---------------- Phase 4: out = attn @ xh (32x128, k=32) --------------
    // lane = hq(8) x dt(4); two d-half passes; thread tile 4h x 16d per pass.
    {
        const int dt = lane & 3;
        const int hq = lane >> 2;
        const int H0 = hq * 4;
        float* outp = out + pos * (NHEADS * HD);

        for (int p = 0; p < 2; p++) {
            unsigned long long acc[4][4][2];
            #pragma unroll
            for (int i = 0; i < 4; i++)
                #pragma unroll
                for (int t = 0; t < 4; t++) { acc[i][t][0] = 0ULL; acc[i][t][1] = 0ULL; }

            #pragma unroll 4
            for (int g = 0; g < 32; g++) {
                float4 av = *reinterpret_cast<const float4*>(&sc[g * SC_ROW + H0]);
                unsigned long long a2[4];
                a2[0] = pack2(av.x, av.x);
                a2[1] = pack2(av.y, av.y);
                a2[2] = pack2(av.z, av.z);
                a2[3] = pack2(av.w, av.w);
                const int sg = (g >> 2) & 7;
                #pragma unroll
                for (int t = 0; t < 4; t++) {
                    const int ch = p * 16 + t * 4 + dt;
                    ulonglong2 bb = *reinterpret_cast<const ulonglong2*>(&xh[g * 32 + (ch ^ sg)]);
                    #pragma unroll
                    for (int i = 0; i < 4; i++) {
                        fma2(acc[i][t][0], a2[i], bb.x);
                        fma2(acc[i][t][1], a2[i], bb.y);
                    }
                }
            }

            #pragma unroll
            for (int i = 0; i < 4; i++)
                #pragma unroll
                for (int t = 0; t < 4; t++) {
                    const int ch = p * 16 + t * 4 + dt;
                    float2 u0 = unpack2(acc[i][t][0]);
                    float2 u1 = unpack2(acc[i][t][1]);
                    *reinterpret_cast<float4*>(&outp[(H0 + i) * HD + ch * 4])
                        = make_float4(u0.x, u0.y, u1.x, u1.y);
                }
        }
    }
}

extern "C" void kernel_launch(void* const* d_in, const int* in_sizes, int n_in,
                              void* d_out, int out_size) {
    const float* x        = (const float*)d_in[0];
    const float* patterns = (const float*)d_in[1];
    float* out            = (float*)d_out;
    const int positions   = in_sizes[0] / (NHEADS * HD);   // 16384
    const int blocks      = (positions + 1) / 2;
    fq_attn_kernel<<<blocks, 64>>>(x, patterns, out, positions);
}